// round 1
// baseline (speedup 1.0000x reference)
#include <cuda_runtime.h>
#include <cuda_bf16.h>

#define M_ROWS   16384
#define F_DIM    1024
#define L_LAYERS 5

#define BM 128
#define BN 128
#define BK 8

// Scratch (allocation-free rule: __device__ globals)
__device__ float g_Wp[L_LAYERS * F_DIM * F_DIM];   // 20 MB: W * adj, all layers
__device__ float g_bufA[(size_t)M_ROWS * F_DIM];   // 64 MB ping
__device__ float g_bufB[(size_t)M_ROWS * F_DIM];   // 64 MB pong

// ---- packed f32x2 helpers (sm_103a FFMA2 path) ----
__device__ __forceinline__ unsigned long long pack2(float lo, float hi) {
    unsigned long long r;
    asm("mov.b64 %0, {%1, %2};" : "=l"(r) : "f"(lo), "f"(hi));
    return r;
}
__device__ __forceinline__ void fma2(unsigned long long& d, unsigned long long a,
                                     unsigned long long b) {
    asm("fma.rn.f32x2 %0, %1, %2, %0;" : "+l"(d) : "l"(a), "l"(b));
}
__device__ __forceinline__ float2 unpack2(unsigned long long v) {
    float2 f;
    asm("mov.b64 {%0, %1}, %2;" : "=f"(f.x), "=f"(f.y) : "l"(v));
    return f;
}

// ---- Wp[l] = W[l] * adj (elementwise, float4) ----
__global__ void prep_kernel(const float* __restrict__ W, const float* __restrict__ adj) {
    const int per_layer4 = F_DIM * F_DIM / 4;
    const int total4 = L_LAYERS * per_layer4;
    int idx = blockIdx.x * blockDim.x + threadIdx.x;
    if (idx >= total4) return;
    float4 w = ((const float4*)W)[idx];
    float4 a = ((const float4*)adj)[idx % per_layer4];
    float4 o;
    o.x = w.x * a.x; o.y = w.y * a.y; o.z = w.z * a.z; o.w = w.w * a.w;
    ((float4*)g_Wp)[idx] = o;
}

// ---- fused GEMM: Y = relu(A @ B + bias) + A ----
// A: M x F (h_in, also the residual), B: F x F (Wp layer), Y: M x F
__global__ void __launch_bounds__(256, 2)
gemm_fused_kernel(const float* __restrict__ A, const float* __restrict__ B,
                  const float* __restrict__ bias, float* __restrict__ Y)
{
    __shared__ unsigned long long As2[BK][BM];  // duplicated (a,a) pairs, 8 KB
    __shared__ float Bs[BK][BN];                // 4 KB

    const int tid = threadIdx.x;          // 0..255
    const int tx = tid & 15;              // 16 col-groups of 8 cols
    const int ty = tid >> 4;              // 16 row-groups of 8 rows
    const int blockRow = blockIdx.y * BM;
    const int blockCol = blockIdx.x * BN;

    // A tile loader: 128 rows x 8 k -> one float4 per thread
    const int aRow = tid >> 1;
    const int aCol = (tid & 1) << 2;
    // B tile loader: 8 k x 128 cols -> one float4 per thread
    const int bRow = tid >> 5;
    const int bCol = (tid & 31) << 2;

    const float* Ag = A + (size_t)(blockRow + aRow) * F_DIM + aCol;
    const float* Bg = B + (size_t)bRow * F_DIM + blockCol + bCol;

    unsigned long long acc[8][4];
    #pragma unroll
    for (int i = 0; i < 8; i++)
        #pragma unroll
        for (int j = 0; j < 4; j++) acc[i][j] = 0ULL;

    for (int k0 = 0; k0 < F_DIM; k0 += BK) {
        float4 av = *(const float4*)(Ag + k0);
        float4 bv = *(const float4*)(Bg + (size_t)k0 * F_DIM);
        As2[aCol + 0][aRow] = pack2(av.x, av.x);
        As2[aCol + 1][aRow] = pack2(av.y, av.y);
        As2[aCol + 2][aRow] = pack2(av.z, av.z);
        As2[aCol + 3][aRow] = pack2(av.w, av.w);
        *(float4*)&Bs[bRow][bCol] = bv;
        __syncthreads();

        #pragma unroll
        for (int kk = 0; kk < BK; kk++) {
            unsigned long long a[8], b[4];
            const ulonglong2* ap = (const ulonglong2*)&As2[kk][ty * 8];
            ulonglong2 a01 = ap[0], a23 = ap[1], a45 = ap[2], a67 = ap[3];
            a[0] = a01.x; a[1] = a01.y; a[2] = a23.x; a[3] = a23.y;
            a[4] = a45.x; a[5] = a45.y; a[6] = a67.x; a[7] = a67.y;
            const ulonglong2* bp = (const ulonglong2*)&Bs[kk][tx * 8];
            ulonglong2 b01 = bp[0], b23 = bp[1];
            b[0] = b01.x; b[1] = b01.y; b[2] = b23.x; b[3] = b23.y;
            #pragma unroll
            for (int i = 0; i < 8; i++)
                #pragma unroll
                for (int j = 0; j < 4; j++)
                    fma2(acc[i][j], a[i], b[j]);
        }
        __syncthreads();
    }

    // epilogue: bias + relu + residual
    const int colBase = blockCol + tx * 8;
    float bias8[8];
    *(float4*)&bias8[0] = *(const float4*)(bias + colBase);
    *(float4*)&bias8[4] = *(const float4*)(bias + colBase + 4);

    #pragma unroll
    for (int i = 0; i < 8; i++) {
        const int row = blockRow + ty * 8 + i;
        const float* hptr = A + (size_t)row * F_DIM + colBase;
        float4 h0 = *(const float4*)(hptr);
        float4 h1 = *(const float4*)(hptr + 4);
        float hv[8] = {h0.x, h0.y, h0.z, h0.w, h1.x, h1.y, h1.z, h1.w};
        float out[8];
        #pragma unroll
        for (int j = 0; j < 4; j++) {
            float2 c = unpack2(acc[i][j]);
            out[2*j]   = fmaxf(c.x + bias8[2*j],   0.0f) + hv[2*j];
            out[2*j+1] = fmaxf(c.y + bias8[2*j+1], 0.0f) + hv[2*j+1];
        }
        float* yptr = Y + (size_t)row * F_DIM + colBase;
        *(float4*)yptr       = make_float4(out[0], out[1], out[2], out[3]);
        *(float4*)(yptr + 4) = make_float4(out[4], out[5], out[6], out[7]);
    }
}

// ---- LayerNorm over F (no affine), in-place capable ----
__global__ void ln_kernel(const float* __restrict__ Yin, float* __restrict__ Yout) {
    const int row = blockIdx.x;
    float4 v = ((const float4*)(Yin + (size_t)row * F_DIM))[threadIdx.x];
    float s  = v.x + v.y + v.z + v.w;
    float ss = v.x*v.x + v.y*v.y + v.z*v.z + v.w*v.w;
    #pragma unroll
    for (int o = 16; o > 0; o >>= 1) {
        s  += __shfl_down_sync(0xffffffffu, s,  o);
        ss += __shfl_down_sync(0xffffffffu, ss, o);
    }
    __shared__ float sh_s[8], sh_ss[8];
    const int warp = threadIdx.x >> 5, lane = threadIdx.x & 31;
    if (lane == 0) { sh_s[warp] = s; sh_ss[warp] = ss; }
    __syncthreads();
    float st = 0.0f, sst = 0.0f;
    #pragma unroll
    for (int w = 0; w < 8; w++) { st += sh_s[w]; sst += sh_ss[w]; }
    const float inv = 1.0f / (float)F_DIM;
    const float mu  = st * inv;
    const float var = sst * inv - mu * mu;
    const float r   = rsqrtf(var + 1e-5f);
    v.x = (v.x - mu) * r;
    v.y = (v.y - mu) * r;
    v.z = (v.z - mu) * r;
    v.w = (v.w - mu) * r;
    ((float4*)(Yout + (size_t)row * F_DIM))[threadIdx.x] = v;
}

extern "C" void kernel_launch(void* const* d_in, const int* in_sizes, int n_in,
                              void* d_out, int out_size) {
    const float* x    = (const float*)d_in[0];   // (16384, 1024)
    const float* adj  = (const float*)d_in[1];   // (1024, 1024)
    const float* W    = (const float*)d_in[2];   // (5, 1024, 1024)
    const float* bias = (const float*)d_in[3];   // (5, 1024)
    float* out = (float*)d_out;

    float *wp = nullptr, *bufA = nullptr, *bufB = nullptr;
    cudaGetSymbolAddress((void**)&wp,   g_Wp);
    cudaGetSymbolAddress((void**)&bufA, g_bufA);
    cudaGetSymbolAddress((void**)&bufB, g_bufB);

    const int total4 = L_LAYERS * F_DIM * F_DIM / 4;
    prep_kernel<<<(total4 + 255) / 256, 256>>>(W, adj);

    const float* hin = x;
    for (int l = 0; l < L_LAYERS; l++) {
        float* yout = (l == L_LAYERS - 1) ? out : ((l & 1) == 0 ? bufA : bufB);
        dim3 grid(F_DIM / BN, M_ROWS / BM);  // (8, 128)
        gemm_fused_kernel<<<grid, 256>>>(hin, wp + (size_t)l * F_DIM * F_DIM,
                                         bias + l * F_DIM, yout);
        ln_kernel<<<M_ROWS, 256>>>(yout, yout);
        hin = yout;
    }
}

// round 3
// speedup vs baseline: 2.3815x; 2.3815x over previous
#include <cuda_runtime.h>
#include <cuda_bf16.h>
#include <cstdint>

#define M_ROWS   16384
#define F_DIM    1024
#define L_LAYERS 5

#define BM 128
#define BN 128
#define BK 32
#define NCHUNK (F_DIM / BK)   // 32
#define THREADS 256
#define STAGES 3

// smem geometry: 4 tiles per stage (Ahi, Alo, Bhi, Blo), each 128 rows x 32 bf16,
// row padded to 80 bytes for conflict-free ldmatrix.
#define ROW_BYTES   80
#define TILE_BYTES  (128 * ROW_BYTES)       // 10240
#define AHI_OFF     0u
#define ALO_OFF     (1u * TILE_BYTES)
#define BHI_OFF     (2u * TILE_BYTES)
#define BLO_OFF     (3u * TILE_BYTES)
#define STAGE_BYTES (4u * TILE_BYTES)       // 40960
#define SMEM_TOTAL  (STAGES * STAGE_BYTES)  // 122880

// ---------------- scratch (__device__ globals; no allocation) ----------------
__device__ __nv_bfloat16 g_Bt_hi[(size_t)L_LAYERS * F_DIM * F_DIM]; // 10 MB  (W*adj)^T hi
__device__ __nv_bfloat16 g_Bt_lo[(size_t)L_LAYERS * F_DIM * F_DIM]; // 10 MB
__device__ __nv_bfloat16 g_hi[(size_t)M_ROWS * F_DIM];              // 32 MB
__device__ __nv_bfloat16 g_lo[(size_t)M_ROWS * F_DIM];              // 32 MB
__device__ float g_bufA[(size_t)M_ROWS * F_DIM];                    // 64 MB  ypre
__device__ float g_bufB[(size_t)M_ROWS * F_DIM];                    // 64 MB  normalized h

// ---------------- helpers ----------------
__device__ __forceinline__ uint32_t smem_u32(const void* p) {
    uint32_t a;
    asm("{ .reg .u64 t; cvta.to.shared.u64 t, %1; cvt.u32.u64 %0, t; }" : "=r"(a) : "l"(p));
    return a;
}
__device__ __forceinline__ void cp_async16(uint32_t dst, const void* src) {
    asm volatile("cp.async.cg.shared.global [%0], [%1], 16;" :: "r"(dst), "l"(src));
}
#define CP_COMMIT()  asm volatile("cp.async.commit_group;")
#define CP_WAIT(n)   asm volatile("cp.async.wait_group %0;" :: "n"(n))

#define LDSM_X4(r, addr) \
    asm volatile("ldmatrix.sync.aligned.m8n8.x4.shared.b16 {%0,%1,%2,%3}, [%4];" \
        : "=r"((r)[0]), "=r"((r)[1]), "=r"((r)[2]), "=r"((r)[3]) : "r"(addr))

__device__ __forceinline__ void mma_bf16(float* d, const uint32_t* a,
                                         uint32_t b0, uint32_t b1) {
    asm volatile(
        "mma.sync.aligned.m16n8k16.row.col.f32.bf16.bf16.f32 "
        "{%0,%1,%2,%3}, {%4,%5,%6,%7}, {%8,%9}, {%0,%1,%2,%3};"
        : "+f"(d[0]), "+f"(d[1]), "+f"(d[2]), "+f"(d[3])
        : "r"(a[0]), "r"(a[1]), "r"(a[2]), "r"(a[3]), "r"(b0), "r"(b1));
}

// ---------------- prep: Bt_{hi,lo}[l][n][k] = split(W[l][k][n] * adj[k][n]) ----------------
__global__ void prep_kernel(const float* __restrict__ W, const float* __restrict__ adj) {
    __shared__ float tile[32][33];
    const int l = blockIdx.z;
    const int kb = blockIdx.x * 32;
    const int nb = blockIdx.y * 32;
    #pragma unroll
    for (int i = 0; i < 4; i++) {
        int k = kb + threadIdx.y + i * 8;
        int n = nb + threadIdx.x;
        tile[threadIdx.y + i * 8][threadIdx.x] =
            W[((size_t)l * F_DIM + k) * F_DIM + n] * adj[(size_t)k * F_DIM + n];
    }
    __syncthreads();
    #pragma unroll
    for (int i = 0; i < 4; i++) {
        int n = nb + threadIdx.y + i * 8;
        int k = kb + threadIdx.x;
        float v = tile[threadIdx.x][threadIdx.y + i * 8];
        __nv_bfloat16 h = __float2bfloat16(v);
        float rem = v - __bfloat162float(h);
        size_t o = ((size_t)l * F_DIM + n) * F_DIM + k;
        g_Bt_hi[o] = h;
        g_Bt_lo[o] = __float2bfloat16(rem);
    }
}

// ---------------- split x -> hi/lo ----------------
__global__ void split_kernel(const float* __restrict__ X) {
    size_t idx = (size_t)blockIdx.x * blockDim.x + threadIdx.x;   // float4 index
    float4 v = ((const float4*)X)[idx];
    __nv_bfloat16 h0 = __float2bfloat16(v.x), h1 = __float2bfloat16(v.y);
    __nv_bfloat16 h2 = __float2bfloat16(v.z), h3 = __float2bfloat16(v.w);
    float l0 = v.x - __bfloat162float(h0), l1 = v.y - __bfloat162float(h1);
    float l2 = v.z - __bfloat162float(h2), l3 = v.w - __bfloat162float(h3);
    __nv_bfloat162 hp0{h0, h1}, hp1{h2, h3};
    __nv_bfloat162 lp0{__float2bfloat16(l0), __float2bfloat16(l1)};
    __nv_bfloat162 lp1{__float2bfloat16(l2), __float2bfloat16(l3)};
    uint2 hu, lu;
    hu.x = *(uint32_t*)&hp0; hu.y = *(uint32_t*)&hp1;
    lu.x = *(uint32_t*)&lp0; lu.y = *(uint32_t*)&lp1;
    ((uint2*)g_hi)[idx] = hu;
    ((uint2*)g_lo)[idx] = lu;
}

// ---------------- GEMM: Y = relu(Ahi/lo @ Bhi/lo + bias) + Hres ----------------
__global__ void __launch_bounds__(THREADS, 1)
gemm_mma_kernel(const __nv_bfloat16* __restrict__ Ahi, const __nv_bfloat16* __restrict__ Alo,
                const float* __restrict__ Hres,
                const __nv_bfloat16* __restrict__ Bhi, const __nv_bfloat16* __restrict__ Blo,
                const float* __restrict__ bias, float* __restrict__ Y)
{
    extern __shared__ char smem[];
    const uint32_t sb = smem_u32(smem);
    const int tid = threadIdx.x;
    const int wid = tid >> 5;
    const int lid = tid & 31;
    const int warpM = wid & 1;     // 2 warps in M
    const int warpN = wid >> 1;    // 4 warps in N
    const int blockRow = blockIdx.y * BM;
    const int blockCol = blockIdx.x * BN;

    const char* gAh = (const char*)(Ahi + (size_t)blockRow * F_DIM);
    const char* gAl = (const char*)(Alo + (size_t)blockRow * F_DIM);
    const char* gBh = (const char*)(Bhi + (size_t)blockCol * F_DIM);
    const char* gBl = (const char*)(Blo + (size_t)blockCol * F_DIM);

    // per-thread cp.async geometry: 16B unit u = tid + 256*i (i<2), row = u>>2, c16 = u&3
    auto load_stage = [&](int c, int s) {
        const int k0b = c * BK * 2;                   // byte offset along k
        const uint32_t base = sb + (uint32_t)s * STAGE_BYTES;
        #pragma unroll
        for (int i = 0; i < 2; i++) {
            const int u = tid + 256 * i;
            const int r = u >> 2;
            const int c16 = u & 3;
            const uint32_t soff = (uint32_t)(r * ROW_BYTES + c16 * 16);
            const size_t goff = (size_t)r * (F_DIM * 2) + k0b + c16 * 16;
            cp_async16(base + AHI_OFF + soff, gAh + goff);
            cp_async16(base + ALO_OFF + soff, gAl + goff);
            cp_async16(base + BHI_OFF + soff, gBh + goff);
            cp_async16(base + BLO_OFF + soff, gBl + goff);
        }
    };

    float acc[4][4][4];
    #pragma unroll
    for (int mt = 0; mt < 4; mt++)
        #pragma unroll
        for (int nt = 0; nt < 4; nt++)
            #pragma unroll
            for (int i = 0; i < 4; i++) acc[mt][nt][i] = 0.f;

    load_stage(0, 0); CP_COMMIT();
    load_stage(1, 1); CP_COMMIT();

    // ldmatrix base addresses (row = lane%16, 16B chunk = lane/16)
    const uint32_t aRowOff = (uint32_t)((warpM * 64 + (lid & 15)) * ROW_BYTES + ((lid >> 4) << 4));
    const uint32_t bRowOff = (uint32_t)((warpN * 32 + (lid & 15)) * ROW_BYTES + ((lid >> 4) << 4));

    for (int c = 0; c < NCHUNK; ++c) {
        if (c + 1 < NCHUNK) { CP_WAIT(1); } else { CP_WAIT(0); }
        __syncthreads();
        if (c + 2 < NCHUNK) { load_stage(c + 2, (c + 2) % STAGES); CP_COMMIT(); }

        const uint32_t stage = sb + (uint32_t)(c % STAGES) * STAGE_BYTES;
        #pragma unroll
        for (int kh = 0; kh < 2; kh++) {
            const uint32_t kb = (uint32_t)(kh * 32);  // 16 bf16 = 32B
            uint32_t ah[4][4], al[4][4], bh[2][4], bl[2][4];
            #pragma unroll
            for (int mt = 0; mt < 4; mt++) {
                LDSM_X4(ah[mt], stage + AHI_OFF + aRowOff + (uint32_t)(mt * 16 * ROW_BYTES) + kb);
                LDSM_X4(al[mt], stage + ALO_OFF + aRowOff + (uint32_t)(mt * 16 * ROW_BYTES) + kb);
            }
            #pragma unroll
            for (int g = 0; g < 2; g++) {
                LDSM_X4(bh[g], stage + BHI_OFF + bRowOff + (uint32_t)(g * 16 * ROW_BYTES) + kb);
                LDSM_X4(bl[g], stage + BLO_OFF + bRowOff + (uint32_t)(g * 16 * ROW_BYTES) + kb);
            }
            #pragma unroll
            for (int mt = 0; mt < 4; mt++) {
                #pragma unroll
                for (int nt = 0; nt < 4; nt++) {
                    const int g = nt >> 1, h = nt & 1;
                    mma_bf16(acc[mt][nt], ah[mt], bh[g][h], bh[g][h + 2]);
                    mma_bf16(acc[mt][nt], ah[mt], bl[g][h], bl[g][h + 2]);
                    mma_bf16(acc[mt][nt], al[mt], bh[g][h], bh[g][h + 2]);
                }
            }
        }
    }

    // ---- epilogue: bias + relu + residual, straight from registers ----
    const int lane4 = lid >> 2;          // 0..7
    const int lanec = (lid & 3) * 2;
    float2 bv[4];
    #pragma unroll
    for (int nt = 0; nt < 4; nt++)
        bv[nt] = *(const float2*)(bias + blockCol + warpN * 32 + nt * 8 + lanec);

    #pragma unroll
    for (int mt = 0; mt < 4; mt++) {
        const int r0 = blockRow + warpM * 64 + mt * 16 + lane4;
        const int r1 = r0 + 8;
        #pragma unroll
        for (int nt = 0; nt < 4; nt++) {
            const int col = blockCol + warpN * 32 + nt * 8 + lanec;
            const size_t o0 = (size_t)r0 * F_DIM + col;
            const size_t o1 = (size_t)r1 * F_DIM + col;
            float2 h0 = *(const float2*)(Hres + o0);
            float2 h1 = *(const float2*)(Hres + o1);
            float* a4 = acc[mt][nt];
            float2 y0, y1;
            y0.x = fmaxf(a4[0] + bv[nt].x, 0.f) + h0.x;
            y0.y = fmaxf(a4[1] + bv[nt].y, 0.f) + h0.y;
            y1.x = fmaxf(a4[2] + bv[nt].x, 0.f) + h1.x;
            y1.y = fmaxf(a4[3] + bv[nt].y, 0.f) + h1.y;
            *(float2*)(Y + o0) = y0;
            *(float2*)(Y + o1) = y1;
        }
    }
}

// ---------------- LayerNorm (+ optional split for next layer) ----------------
__global__ void ln_split_kernel(const float* __restrict__ Yin, float* __restrict__ Yout,
                                int do_split) {
    const int row = blockIdx.x;
    const size_t base4 = (size_t)row * (F_DIM / 4);
    float4 v = ((const float4*)Yin)[base4 + threadIdx.x];
    float s  = v.x + v.y + v.z + v.w;
    float ss = v.x * v.x + v.y * v.y + v.z * v.z + v.w * v.w;
    #pragma unroll
    for (int o = 16; o > 0; o >>= 1) {
        s  += __shfl_down_sync(0xffffffffu, s,  o);
        ss += __shfl_down_sync(0xffffffffu, ss, o);
    }
    __shared__ float sh_s[8], sh_ss[8];
    const int warp = threadIdx.x >> 5, lane = threadIdx.x & 31;
    if (lane == 0) { sh_s[warp] = s; sh_ss[warp] = ss; }
    __syncthreads();
    float st = 0.f, sst = 0.f;
    #pragma unroll
    for (int w = 0; w < 8; w++) { st += sh_s[w]; sst += sh_ss[w]; }
    const float inv = 1.0f / (float)F_DIM;
    const float mu  = st * inv;
    const float var = sst * inv - mu * mu;
    const float r   = rsqrtf(var + 1e-5f);
    v.x = (v.x - mu) * r; v.y = (v.y - mu) * r;
    v.z = (v.z - mu) * r; v.w = (v.w - mu) * r;
    ((float4*)Yout)[base4 + threadIdx.x] = v;
    if (do_split) {
        __nv_bfloat16 h0 = __float2bfloat16(v.x), h1 = __float2bfloat16(v.y);
        __nv_bfloat16 h2 = __float2bfloat16(v.z), h3 = __float2bfloat16(v.w);
        float l0 = v.x - __bfloat162float(h0), l1 = v.y - __bfloat162float(h1);
        float l2 = v.z - __bfloat162float(h2), l3 = v.w - __bfloat162float(h3);
        __nv_bfloat162 hp0{h0, h1}, hp1{h2, h3};
        __nv_bfloat162 lp0{__float2bfloat16(l0), __float2bfloat16(l1)};
        __nv_bfloat162 lp1{__float2bfloat16(l2), __float2bfloat16(l3)};
        uint2 hu, lu;
        hu.x = *(uint32_t*)&hp0; hu.y = *(uint32_t*)&hp1;
        lu.x = *(uint32_t*)&lp0; lu.y = *(uint32_t*)&lp1;
        ((uint2*)g_hi)[base4 + threadIdx.x] = hu;
        ((uint2*)g_lo)[base4 + threadIdx.x] = lu;
    }
}

// ---------------- launch ----------------
extern "C" void kernel_launch(void* const* d_in, const int* in_sizes, int n_in,
                              void* d_out, int out_size) {
    const float* x    = (const float*)d_in[0];   // (16384, 1024)
    const float* adj  = (const float*)d_in[1];   // (1024, 1024)
    const float* W    = (const float*)d_in[2];   // (5, 1024, 1024)
    const float* bias = (const float*)d_in[3];   // (5, 1024)
    float* out = (float*)d_out;

    cudaFuncSetAttribute(gemm_mma_kernel,
                         cudaFuncAttributeMaxDynamicSharedMemorySize, SMEM_TOTAL);

    __nv_bfloat16 *bth, *btl, *ahi, *alo;
    float *bufA, *bufB;
    cudaGetSymbolAddress((void**)&bth,  g_Bt_hi);
    cudaGetSymbolAddress((void**)&btl,  g_Bt_lo);
    cudaGetSymbolAddress((void**)&ahi,  g_hi);
    cudaGetSymbolAddress((void**)&alo,  g_lo);
    cudaGetSymbolAddress((void**)&bufA, g_bufA);
    cudaGetSymbolAddress((void**)&bufB, g_bufB);

    prep_kernel<<<dim3(F_DIM / 32, F_DIM / 32, L_LAYERS), dim3(32, 8)>>>(W, adj);
    split_kernel<<<(M_ROWS * F_DIM / 4) / 256, 256>>>(x);

    const float* h = x;
    for (int l = 0; l < L_LAYERS; ++l) {
        const size_t bo = (size_t)l * F_DIM * F_DIM;
        gemm_mma_kernel<<<dim3(F_DIM / BN, M_ROWS / BM), THREADS, SMEM_TOTAL>>>(
            ahi, alo, h, bth + bo, btl + bo, bias + (size_t)l * F_DIM, bufA);
        const int last = (l == L_LAYERS - 1);
        ln_split_kernel<<<M_ROWS, 256>>>(bufA, last ? out : bufB, !last);
        h = bufB;
    }
}

// round 4
// speedup vs baseline: 3.3207x; 1.3943x over previous
#include <cuda_runtime.h>
#include <cuda_fp16.h>
#include <cstdint>

#define M_ROWS   16384
#define F_DIM    1024
#define L_LAYERS 5

#define BM 128
#define BN 128
#define BK 32
#define NCHUNK (F_DIM / BK)   // 32
#define THREADS 256
#define STAGES 4

// smem: 3 tiles per stage (A, Bhi, Blo), each 128 rows x 32 fp16 (64B) padded to 80B rows.
#define ROW_BYTES   80
#define TILE_BYTES  (128 * ROW_BYTES)       // 10240
#define A_OFF       0u
#define BH_OFF      (1u * TILE_BYTES)
#define BL_OFF      (2u * TILE_BYTES)
#define STAGE_BYTES (3u * TILE_BYTES)       // 30720
#define SMEM_TOTAL  (STAGES * STAGE_BYTES)  // 122880

// ---------------- scratch ----------------
__device__ __half g_Bh[(size_t)L_LAYERS * F_DIM * F_DIM];  // 10 MB  (W*adj)^T hi
__device__ __half g_Bl[(size_t)L_LAYERS * F_DIM * F_DIM];  // 10 MB  (W*adj)^T lo
__device__ __half g_A [(size_t)M_ROWS * F_DIM];            // 32 MB  current h (fp16)
__device__ float g_bufA[(size_t)M_ROWS * F_DIM];           // 64 MB  ypre
__device__ float g_bufB[(size_t)M_ROWS * F_DIM];           // 64 MB  normalized h (fp32)

// ---------------- helpers ----------------
__device__ __forceinline__ uint32_t smem_u32(const void* p) {
    uint32_t a;
    asm("{ .reg .u64 t; cvta.to.shared.u64 t, %1; cvt.u32.u64 %0, t; }" : "=r"(a) : "l"(p));
    return a;
}
__device__ __forceinline__ void cp_async16(uint32_t dst, const void* src) {
    asm volatile("cp.async.cg.shared.global [%0], [%1], 16;" :: "r"(dst), "l"(src));
}
#define CP_COMMIT()  asm volatile("cp.async.commit_group;")
#define CP_WAIT(n)   asm volatile("cp.async.wait_group %0;" :: "n"(n))

#define LDSM_X4(r, addr) \
    asm volatile("ldmatrix.sync.aligned.m8n8.x4.shared.b16 {%0,%1,%2,%3}, [%4];" \
        : "=r"((r)[0]), "=r"((r)[1]), "=r"((r)[2]), "=r"((r)[3]) : "r"(addr))

__device__ __forceinline__ void mma_f16(float* d, const uint32_t* a,
                                        uint32_t b0, uint32_t b1) {
    asm volatile(
        "mma.sync.aligned.m16n8k16.row.col.f32.f16.f16.f32 "
        "{%0,%1,%2,%3}, {%4,%5,%6,%7}, {%8,%9}, {%0,%1,%2,%3};"
        : "+f"(d[0]), "+f"(d[1]), "+f"(d[2]), "+f"(d[3])
        : "r"(a[0]), "r"(a[1]), "r"(a[2]), "r"(a[3]), "r"(b0), "r"(b1));
}

// ---------------- prep: B{h,l}[l][n][k] = split_fp16(W[l][k][n] * adj[k][n]) ----------------
__global__ void prep_kernel(const float* __restrict__ W, const float* __restrict__ adj) {
    __shared__ float tile[32][33];
    const int l = blockIdx.z;
    const int kb = blockIdx.x * 32;
    const int nb = blockIdx.y * 32;
    #pragma unroll
    for (int i = 0; i < 4; i++) {
        int k = kb + threadIdx.y + i * 8;
        int n = nb + threadIdx.x;
        tile[threadIdx.y + i * 8][threadIdx.x] =
            W[((size_t)l * F_DIM + k) * F_DIM + n] * adj[(size_t)k * F_DIM + n];
    }
    __syncthreads();
    #pragma unroll
    for (int i = 0; i < 4; i++) {
        int n = nb + threadIdx.y + i * 8;
        int k = kb + threadIdx.x;
        float v = tile[threadIdx.x][threadIdx.y + i * 8];
        __half h = __float2half(v);
        float rem = v - __half2float(h);
        size_t o = ((size_t)l * F_DIM + n) * F_DIM + k;
        g_Bh[o] = h;
        g_Bl[o] = __float2half(rem);
    }
}

// ---------------- split x -> fp16 (elementwise; two launches for profile alignment) ----
__global__ void tohalf_kernel(const float* __restrict__ X, size_t off4) {
    size_t idx = off4 + (size_t)blockIdx.x * blockDim.x + threadIdx.x;  // 4-elem unit
    float4 v = ((const float4*)X)[idx];
    __half2 p0{__float2half(v.x), __float2half(v.y)};
    __half2 p1{__float2half(v.z), __float2half(v.w)};
    uint2 u;
    u.x = *(uint32_t*)&p0; u.y = *(uint32_t*)&p1;
    ((uint2*)g_A)[idx] = u;
}

// ---------------- GEMM: Y = relu(A @ (Bh+Bl) + bias) + Hres ----------------
__global__ void __launch_bounds__(THREADS, 1)
gemm_mma_kernel(const __half* __restrict__ A, const float* __restrict__ Hres,
                const __half* __restrict__ Bh, const __half* __restrict__ Bl,
                const float* __restrict__ bias, float* __restrict__ Y)
{
    extern __shared__ char smem[];
    const uint32_t sb = smem_u32(smem);
    const int tid = threadIdx.x;
    const int wid = tid >> 5;
    const int lid = tid & 31;
    const int warpM = wid & 1;     // 2 warps in M
    const int warpN = wid >> 1;    // 4 warps in N
    const int blockRow = blockIdx.y * BM;
    const int blockCol = blockIdx.x * BN;

    const char* gA  = (const char*)(A  + (size_t)blockRow * F_DIM);
    const char* gBh = (const char*)(Bh + (size_t)blockCol * F_DIM);
    const char* gBl = (const char*)(Bl + (size_t)blockCol * F_DIM);

    // 16B chunks: tile has 128 rows x 4 chunks = 512; 256 threads -> 2 per tile
    auto load_stage = [&](int c, int s) {
        const int k0b = c * BK * 2;                   // byte offset along k
        const uint32_t base = sb + (uint32_t)s * STAGE_BYTES;
        #pragma unroll
        for (int i = 0; i < 2; i++) {
            const int u = tid + 256 * i;
            const int r = u >> 2;
            const int c16 = u & 3;
            const uint32_t soff = (uint32_t)(r * ROW_BYTES + c16 * 16);
            const size_t goff = (size_t)r * (F_DIM * 2) + k0b + c16 * 16;
            cp_async16(base + A_OFF  + soff, gA  + goff);
            cp_async16(base + BH_OFF + soff, gBh + goff);
            cp_async16(base + BL_OFF + soff, gBl + goff);
        }
    };

    float acc[4][4][4];
    #pragma unroll
    for (int mt = 0; mt < 4; mt++)
        #pragma unroll
        for (int nt = 0; nt < 4; nt++)
            #pragma unroll
            for (int i = 0; i < 4; i++) acc[mt][nt][i] = 0.f;

    load_stage(0, 0); CP_COMMIT();
    load_stage(1, 1); CP_COMMIT();
    load_stage(2, 2); CP_COMMIT();

    const uint32_t aRowOff = (uint32_t)((warpM * 64 + (lid & 15)) * ROW_BYTES + ((lid >> 4) << 4));
    const uint32_t bRowOff = (uint32_t)((warpN * 32 + (lid & 15)) * ROW_BYTES + ((lid >> 4) << 4));

    for (int c = 0; c < NCHUNK; ++c) {
        CP_WAIT(2);               // stage c complete (3 groups always outstanding)
        __syncthreads();
        if (c + 3 < NCHUNK) load_stage(c + 3, (c + 3) & 3);
        CP_COMMIT();              // commit every iter (possibly empty) for uniform accounting

        const uint32_t stage = sb + (uint32_t)(c & 3) * STAGE_BYTES;
        #pragma unroll
        for (int kh = 0; kh < 2; kh++) {
            const uint32_t kb = (uint32_t)(kh * 32);  // 16 fp16 = 32B
            uint32_t a[4][4], bh[2][4], bl[2][4];
            #pragma unroll
            for (int mt = 0; mt < 4; mt++)
                LDSM_X4(a[mt], stage + A_OFF + aRowOff + (uint32_t)(mt * 16 * ROW_BYTES) + kb);
            #pragma unroll
            for (int g = 0; g < 2; g++) {
                LDSM_X4(bh[g], stage + BH_OFF + bRowOff + (uint32_t)(g * 16 * ROW_BYTES) + kb);
                LDSM_X4(bl[g], stage + BL_OFF + bRowOff + (uint32_t)(g * 16 * ROW_BYTES) + kb);
            }
            #pragma unroll
            for (int mt = 0; mt < 4; mt++) {
                #pragma unroll
                for (int nt = 0; nt < 4; nt++) {
                    const int g = nt >> 1, h = nt & 1;
                    mma_f16(acc[mt][nt], a[mt], bh[g][h], bh[g][h + 2]);
                    mma_f16(acc[mt][nt], a[mt], bl[g][h], bl[g][h + 2]);
                }
            }
        }
    }

    // ---- epilogue: bias + relu + residual ----
    const int lane4 = lid >> 2;
    const int lanec = (lid & 3) * 2;
    float2 bv[4];
    #pragma unroll
    for (int nt = 0; nt < 4; nt++)
        bv[nt] = *(const float2*)(bias + blockCol + warpN * 32 + nt * 8 + lanec);

    #pragma unroll
    for (int mt = 0; mt < 4; mt++) {
        const int r0 = blockRow + warpM * 64 + mt * 16 + lane4;
        const int r1 = r0 + 8;
        #pragma unroll
        for (int nt = 0; nt < 4; nt++) {
            const int col = blockCol + warpN * 32 + nt * 8 + lanec;
            const size_t o0 = (size_t)r0 * F_DIM + col;
            const size_t o1 = (size_t)r1 * F_DIM + col;
            float2 h0 = *(const float2*)(Hres + o0);
            float2 h1 = *(const float2*)(Hres + o1);
            float* a4 = acc[mt][nt];
            float2 y0, y1;
            y0.x = fmaxf(a4[0] + bv[nt].x, 0.f) + h0.x;
            y0.y = fmaxf(a4[1] + bv[nt].y, 0.f) + h0.y;
            y1.x = fmaxf(a4[2] + bv[nt].x, 0.f) + h1.x;
            y1.y = fmaxf(a4[3] + bv[nt].y, 0.f) + h1.y;
            *(float2*)(Y + o0) = y0;
            *(float2*)(Y + o1) = y1;
        }
    }
}

// ---------------- LayerNorm (+ optional fp16 store for next layer's A) ----------------
__global__ void ln_split_kernel(const float* __restrict__ Yin, float* __restrict__ Yout,
                                int do_half) {
    const int row = blockIdx.x;
    const size_t base4 = (size_t)row * (F_DIM / 4);
    float4 v = ((const float4*)Yin)[base4 + threadIdx.x];
    float s  = v.x + v.y + v.z + v.w;
    float ss = v.x * v.x + v.y * v.y + v.z * v.z + v.w * v.w;
    #pragma unroll
    for (int o = 16; o > 0; o >>= 1) {
        s  += __shfl_down_sync(0xffffffffu, s,  o);
        ss += __shfl_down_sync(0xffffffffu, ss, o);
    }
    __shared__ float sh_s[8], sh_ss[8];
    const int warp = threadIdx.x >> 5, lane = threadIdx.x & 31;
    if (lane == 0) { sh_s[warp] = s; sh_ss[warp] = ss; }
    __syncthreads();
    float st = 0.f, sst = 0.f;
    #pragma unroll
    for (int w = 0; w < 8; w++) { st += sh_s[w]; sst += sh_ss[w]; }
    const float inv = 1.0f / (float)F_DIM;
    const float mu  = st * inv;
    const float var = sst * inv - mu * mu;
    const float r   = rsqrtf(var + 1e-5f);
    v.x = (v.x - mu) * r; v.y = (v.y - mu) * r;
    v.z = (v.z - mu) * r; v.w = (v.w - mu) * r;
    ((float4*)Yout)[base4 + threadIdx.x] = v;
    if (do_half) {
        __half2 p0{__float2half(v.x), __float2half(v.y)};
        __half2 p1{__float2half(v.z), __float2half(v.w)};
        uint2 u;
        u.x = *(uint32_t*)&p0; u.y = *(uint32_t*)&p1;
        ((uint2*)g_A)[base4 + threadIdx.x] = u;
    }
}

// ---------------- launch ----------------
extern "C" void kernel_launch(void* const* d_in, const int* in_sizes, int n_in,
                              void* d_out, int out_size) {
    const float* x    = (const float*)d_in[0];   // (16384, 1024)
    const float* adj  = (const float*)d_in[1];   // (1024, 1024)
    const float* W    = (const float*)d_in[2];   // (5, 1024, 1024)
    const float* bias = (const float*)d_in[3];   // (5, 1024)
    float* out = (float*)d_out;

    cudaFuncSetAttribute(gemm_mma_kernel,
                         cudaFuncAttributeMaxDynamicSharedMemorySize, SMEM_TOTAL);

    __half *bh, *bl, *ah;
    float *bufA, *bufB;
    cudaGetSymbolAddress((void**)&bh,   g_Bh);
    cudaGetSymbolAddress((void**)&bl,   g_Bl);
    cudaGetSymbolAddress((void**)&ah,   g_A);
    cudaGetSymbolAddress((void**)&bufA, g_bufA);
    cudaGetSymbolAddress((void**)&bufB, g_bufB);

    // launch order engineered so ncu (-s 5) profiles a GEMM (index 5 = layer-1 gemm)
    prep_kernel<<<dim3(F_DIM / 32, F_DIM / 32, L_LAYERS), dim3(32, 8)>>>(W, adj);
    const size_t half4 = (size_t)M_ROWS * F_DIM / 4 / 2;   // 4-elem units per half
    tohalf_kernel<<<(int)(half4 / 256), 256>>>(x, 0);
    tohalf_kernel<<<(int)(half4 / 256), 256>>>(x, half4);

    const float* h = x;
    for (int l = 0; l < L_LAYERS; ++l) {
        const size_t bo = (size_t)l * F_DIM * F_DIM;
        gemm_mma_kernel<<<dim3(F_DIM / BN, M_ROWS / BM), THREADS, SMEM_TOTAL>>>(
            ah, h, bh + bo, bl + bo, bias + (size_t)l * F_DIM, bufA);
        const int last = (l == L_LAYERS - 1);
        ln_split_kernel<<<M_ROWS, 256>>>(bufA, last ? out : bufB, !last);
        h = bufB;
    }
}

// round 5
// speedup vs baseline: 3.9162x; 1.1793x over previous
#include <cuda_runtime.h>
#include <cuda_fp16.h>
#include <cstdint>

#define M_ROWS   16384
#define F_DIM    1024
#define L_LAYERS 5

#define BM 128
#define BN 128
#define BK 32
#define NCHUNK (F_DIM / BK)   // 32
#define THREADS 512
#define STAGES 4

// smem: 3 tiles per stage (A, Bhi, Blo), each 128 rows x 32 fp16 (64B) padded to 80B rows.
#define ROW_BYTES   80
#define TILE_BYTES  (128 * ROW_BYTES)       // 10240
#define A_OFF       0u
#define BH_OFF      (1u * TILE_BYTES)
#define BL_OFF      (2u * TILE_BYTES)
#define STAGE_BYTES (3u * TILE_BYTES)       // 30720
#define SMEM_TOTAL  (STAGES * STAGE_BYTES)  // 122880

// ---------------- scratch ----------------
__device__ __half g_Bh[(size_t)L_LAYERS * F_DIM * F_DIM];  // 10 MB  (W*adj)^T hi
__device__ __half g_Bl[(size_t)L_LAYERS * F_DIM * F_DIM];  // 10 MB  (W*adj)^T lo
__device__ __half g_A [(size_t)M_ROWS * F_DIM];            // 32 MB  current h (fp16)
__device__ float g_bufA[(size_t)M_ROWS * F_DIM];           // 64 MB  ypre
__device__ float g_bufB[(size_t)M_ROWS * F_DIM];           // 64 MB  normalized h (fp32)

// ---------------- helpers ----------------
__device__ __forceinline__ uint32_t smem_u32(const void* p) {
    uint32_t a;
    asm("{ .reg .u64 t; cvta.to.shared.u64 t, %1; cvt.u32.u64 %0, t; }" : "=r"(a) : "l"(p));
    return a;
}
__device__ __forceinline__ void cp_async16(uint32_t dst, const void* src) {
    asm volatile("cp.async.cg.shared.global [%0], [%1], 16;" :: "r"(dst), "l"(src));
}
#define CP_COMMIT()  asm volatile("cp.async.commit_group;")
#define CP_WAIT(n)   asm volatile("cp.async.wait_group %0;" :: "n"(n))

#define LDSM_X4(r, addr) \
    asm volatile("ldmatrix.sync.aligned.m8n8.x4.shared.b16 {%0,%1,%2,%3}, [%4];" \
        : "=r"((r)[0]), "=r"((r)[1]), "=r"((r)[2]), "=r"((r)[3]) : "r"(addr))

__device__ __forceinline__ void mma_f16(float* d, const uint32_t* a,
                                        uint32_t b0, uint32_t b1) {
    asm volatile(
        "mma.sync.aligned.m16n8k16.row.col.f32.f16.f16.f32 "
        "{%0,%1,%2,%3}, {%4,%5,%6,%7}, {%8,%9}, {%0,%1,%2,%3};"
        : "+f"(d[0]), "+f"(d[1]), "+f"(d[2]), "+f"(d[3])
        : "r"(a[0]), "r"(a[1]), "r"(a[2]), "r"(a[3]), "r"(b0), "r"(b1));
}

// ---------------- prep: B{h,l}[l][n][k] = split_fp16(W[l][k][n] * adj[k][n]) ----------------
__global__ void prep_kernel(const float* __restrict__ W, const float* __restrict__ adj) {
    __shared__ float tile[32][33];
    const int l = blockIdx.z;
    const int kb = blockIdx.x * 32;
    const int nb = blockIdx.y * 32;
    #pragma unroll
    for (int i = 0; i < 4; i++) {
        int k = kb + threadIdx.y + i * 8;
        int n = nb + threadIdx.x;
        tile[threadIdx.y + i * 8][threadIdx.x] =
            W[((size_t)l * F_DIM + k) * F_DIM + n] * adj[(size_t)k * F_DIM + n];
    }
    __syncthreads();
    #pragma unroll
    for (int i = 0; i < 4; i++) {
        int n = nb + threadIdx.y + i * 8;
        int k = kb + threadIdx.x;
        float v = tile[threadIdx.x][threadIdx.y + i * 8];
        __half h = __float2half(v);
        float rem = v - __half2float(h);
        size_t o = ((size_t)l * F_DIM + n) * F_DIM + k;
        g_Bh[o] = h;
        g_Bl[o] = __float2half(rem);
    }
}

// ---------------- x -> fp16 (two launches so ncu -s 5 hits gemm layer 1) ----
__global__ void tohalf_kernel(const float* __restrict__ X, size_t off4) {
    size_t idx = off4 + (size_t)blockIdx.x * blockDim.x + threadIdx.x;  // 4-elem unit
    float4 v = ((const float4*)X)[idx];
    __half2 p0{__float2half(v.x), __float2half(v.y)};
    __half2 p1{__float2half(v.z), __float2half(v.w)};
    uint2 u;
    u.x = *(uint32_t*)&p0; u.y = *(uint32_t*)&p1;
    ((uint2*)g_A)[idx] = u;
}

// ---------------- GEMM: Y = relu(A @ (Bh+Bl) + bias) + Hres ----------------
__global__ void __launch_bounds__(THREADS, 1)
gemm_mma_kernel(const __half* __restrict__ A, const float* __restrict__ Hres,
                const __half* __restrict__ Bh, const __half* __restrict__ Bl,
                const float* __restrict__ bias, float* __restrict__ Y)
{
    extern __shared__ char smem[];
    const uint32_t sb = smem_u32(smem);
    const int tid = threadIdx.x;
    const int wid = tid >> 5;
    const int lid = tid & 31;
    const int warpM = wid & 3;     // 4 warps in M, tile 32 rows
    const int warpN = wid >> 2;    // 4 warps in N, tile 32 cols
    const int blockRow = blockIdx.y * BM;
    const int blockCol = blockIdx.x * BN;

    const char* gA  = (const char*)(A  + (size_t)blockRow * F_DIM);
    const char* gBh = (const char*)(Bh + (size_t)blockCol * F_DIM);
    const char* gBl = (const char*)(Bl + (size_t)blockCol * F_DIM);

    // 16B chunks: tile = 128 rows x 4 chunks = 512; 512 threads -> 1 per tile
    auto load_stage = [&](int c, int s) {
        const int k0b = c * BK * 2;
        const uint32_t base = sb + (uint32_t)s * STAGE_BYTES;
        const int r = tid >> 2;
        const int c16 = tid & 3;
        const uint32_t soff = (uint32_t)(r * ROW_BYTES + c16 * 16);
        const size_t goff = (size_t)r * (F_DIM * 2) + k0b + c16 * 16;
        cp_async16(base + A_OFF  + soff, gA  + goff);
        cp_async16(base + BH_OFF + soff, gBh + goff);
        cp_async16(base + BL_OFF + soff, gBl + goff);
    };

    float acc[2][4][4];
    #pragma unroll
    for (int mt = 0; mt < 2; mt++)
        #pragma unroll
        for (int nt = 0; nt < 4; nt++)
            #pragma unroll
            for (int i = 0; i < 4; i++) acc[mt][nt][i] = 0.f;

    load_stage(0, 0); CP_COMMIT();
    load_stage(1, 1); CP_COMMIT();
    load_stage(2, 2); CP_COMMIT();

    const uint32_t aRowOff = (uint32_t)((warpM * 32 + (lid & 15)) * ROW_BYTES + ((lid >> 4) << 4));
    const uint32_t bRowOff = (uint32_t)((warpN * 32 + (lid & 15)) * ROW_BYTES + ((lid >> 4) << 4));

    for (int c = 0; c < NCHUNK; ++c) {
        CP_WAIT(2);
        __syncthreads();
        if (c + 3 < NCHUNK) load_stage(c + 3, (c + 3) & 3);
        CP_COMMIT();

        const uint32_t stage = sb + (uint32_t)(c & 3) * STAGE_BYTES;
        #pragma unroll
        for (int kh = 0; kh < 2; kh++) {
            const uint32_t kb = (uint32_t)(kh * 32);  // 16 fp16 = 32B
            uint32_t a[2][4], bh[2][4], bl[2][4];
            #pragma unroll
            for (int mt = 0; mt < 2; mt++)
                LDSM_X4(a[mt], stage + A_OFF + aRowOff + (uint32_t)(mt * 16 * ROW_BYTES) + kb);
            #pragma unroll
            for (int g = 0; g < 2; g++) {
                LDSM_X4(bh[g], stage + BH_OFF + bRowOff + (uint32_t)(g * 16 * ROW_BYTES) + kb);
                LDSM_X4(bl[g], stage + BL_OFF + bRowOff + (uint32_t)(g * 16 * ROW_BYTES) + kb);
            }
            #pragma unroll
            for (int mt = 0; mt < 2; mt++) {
                #pragma unroll
                for (int nt = 0; nt < 4; nt++) {
                    const int g = nt >> 1, h = nt & 1;
                    mma_f16(acc[mt][nt], a[mt], bh[g][h], bh[g][h + 2]);
                    mma_f16(acc[mt][nt], a[mt], bl[g][h], bl[g][h + 2]);
                }
            }
        }
    }

    // ---- epilogue: bias + relu + residual ----
    const int lane4 = lid >> 2;
    const int lanec = (lid & 3) * 2;
    float2 bv[4];
    #pragma unroll
    for (int nt = 0; nt < 4; nt++)
        bv[nt] = *(const float2*)(bias + blockCol + warpN * 32 + nt * 8 + lanec);

    #pragma unroll
    for (int mt = 0; mt < 2; mt++) {
        const int r0 = blockRow + warpM * 32 + mt * 16 + lane4;
        const int r1 = r0 + 8;
        #pragma unroll
        for (int nt = 0; nt < 4; nt++) {
            const int col = blockCol + warpN * 32 + nt * 8 + lanec;
            const size_t o0 = (size_t)r0 * F_DIM + col;
            const size_t o1 = (size_t)r1 * F_DIM + col;
            float2 h0 = *(const float2*)(Hres + o0);
            float2 h1 = *(const float2*)(Hres + o1);
            float* a4 = acc[mt][nt];
            float2 y0, y1;
            y0.x = fmaxf(a4[0] + bv[nt].x, 0.f) + h0.x;
            y0.y = fmaxf(a4[1] + bv[nt].y, 0.f) + h0.y;
            y1.x = fmaxf(a4[2] + bv[nt].x, 0.f) + h1.x;
            y1.y = fmaxf(a4[3] + bv[nt].y, 0.f) + h1.y;
            *(float2*)(Y + o0) = y0;
            *(float2*)(Y + o1) = y1;
        }
    }
}

// ---------------- LayerNorm (+ optional fp16 store for next layer's A) ----------------
__global__ void ln_split_kernel(const float* __restrict__ Yin, float* __restrict__ Yout,
                                int do_half) {
    const int row = blockIdx.x;
    const size_t base4 = (size_t)row * (F_DIM / 4);
    float4 v = ((const float4*)Yin)[base4 + threadIdx.x];
    float s  = v.x + v.y + v.z + v.w;
    float ss = v.x * v.x + v.y * v.y + v.z * v.z + v.w * v.w;
    #pragma unroll
    for (int o = 16; o > 0; o >>= 1) {
        s  += __shfl_down_sync(0xffffffffu, s,  o);
        ss += __shfl_down_sync(0xffffffffu, ss, o);
    }
    __shared__ float sh_s[8], sh_ss[8];
    const int warp = threadIdx.x >> 5, lane = threadIdx.x & 31;
    if (lane == 0) { sh_s[warp] = s; sh_ss[warp] = ss; }
    __syncthreads();
    float st = 0.f, sst = 0.f;
    #pragma unroll
    for (int w = 0; w < 8; w++) { st += sh_s[w]; sst += sh_ss[w]; }
    const float inv = 1.0f / (float)F_DIM;
    const float mu  = st * inv;
    const float var = sst * inv - mu * mu;
    const float r   = rsqrtf(var + 1e-5f);
    v.x = (v.x - mu) * r; v.y = (v.y - mu) * r;
    v.z = (v.z - mu) * r; v.w = (v.w - mu) * r;
    ((float4*)Yout)[base4 + threadIdx.x] = v;
    if (do_half) {
        __half2 p0{__float2half(v.x), __float2half(v.y)};
        __half2 p1{__float2half(v.z), __float2half(v.w)};
        uint2 u;
        u.x = *(uint32_t*)&p0; u.y = *(uint32_t*)&p1;
        ((uint2*)g_A)[base4 + threadIdx.x] = u;
    }
}

// ---------------- launch ----------------
extern "C" void kernel_launch(void* const* d_in, const int* in_sizes, int n_in,
                              void* d_out, int out_size) {
    const float* x    = (const float*)d_in[0];   // (16384, 1024)
    const float* adj  = (const float*)d_in[1];   // (1024, 1024)
    const float* W    = (const float*)d_in[2];   // (5, 1024, 1024)
    const float* bias = (const float*)d_in[3];   // (5, 1024)
    float* out = (float*)d_out;

    cudaFuncSetAttribute(gemm_mma_kernel,
                         cudaFuncAttributeMaxDynamicSharedMemorySize, SMEM_TOTAL);

    __half *bh, *bl, *ah;
    float *bufA, *bufB;
    cudaGetSymbolAddress((void**)&bh,   g_Bh);
    cudaGetSymbolAddress((void**)&bl,   g_Bl);
    cudaGetSymbolAddress((void**)&ah,   g_A);
    cudaGetSymbolAddress((void**)&bufA, g_bufA);
    cudaGetSymbolAddress((void**)&bufB, g_bufB);

    prep_kernel<<<dim3(F_DIM / 32, F_DIM / 32, L_LAYERS), dim3(32, 8)>>>(W, adj);
    const size_t half4 = (size_t)M_ROWS * F_DIM / 4 / 2;
    tohalf_kernel<<<(int)(half4 / 256), 256>>>(x, 0);
    tohalf_kernel<<<(int)(half4 / 256), 256>>>(x, half4);

    const float* h = x;
    for (int l = 0; l < L_LAYERS; ++l) {
        const size_t bo = (size_t)l * F_DIM * F_DIM;
        gemm_mma_kernel<<<dim3(F_DIM / BN, M_ROWS / BM), THREADS, SMEM_TOTAL>>>(
            ah, h, bh + bo, bl + bo, bias + (size_t)l * F_DIM, bufA);
        const int last = (l == L_LAYERS - 1);
        ln_split_kernel<<<M_ROWS, 256>>>(bufA, last ? out : bufB, !last);
        h = bufB;
    }
}